// round 5
// baseline (speedup 1.0000x reference)
#include <cuda_runtime.h>
#include <cstdint>

#define B_ 8192
#define I_ 1024
#define H_ 2048

// fl32(exp(-1/20)) -- compiler rounds the f64 literal to f32 (CR)
#define BETA32 ((float)0.9512294245007140)

// ---------------- device-global scratch (no mallocs allowed) ----------------
__device__ float  g_gen_mem[(size_t)B_ * I_];   // carried gen membrane
__device__ float  g_inf_mem[(size_t)B_ * H_];   // carried inf membrane
__device__ float  g_X1[(size_t)B_ * H_];        // ln(current)
__device__ float  g_X2[(size_t)B_ * I_];        // ln(error)
__device__ float  g_W1T[(size_t)H_ * I_];       // wq transposed: [h][i]  (k-major for GEMM1)
__device__ float  g_WQ[(size_t)I_ * H_];        // wq:            [i][h]  (k-major for GEMM2)
__device__ double g_partials[512];
__device__ float  g_sc[2];                      // [0]=scale, [1]=scale+eps

// ---------------- helpers ----------------
__device__ __forceinline__ double warp_sumd(double v) {
#pragma unroll
    for (int o = 16; o; o >>= 1) v += __shfl_xor_sync(0xffffffffu, v, o);
    return v;
}
__device__ __forceinline__ void ffma2(unsigned long long& d, unsigned long long a,
                                      unsigned long long b) {
    asm volatile("fma.rn.f32x2 %0, %1, %2, %0;" : "+l"(d) : "l"(a), "l"(b));
}
__device__ __forceinline__ unsigned long long dup2(float x) {
    unsigned long long r;
    asm("mov.b64 %0, {%1, %1};" : "=l"(r) : "f"(x));
    return r;
}
__device__ __forceinline__ void cp16(void* sm, const void* gm) {
    uint32_t s = (uint32_t)__cvta_generic_to_shared(sm);
    asm volatile("cp.async.cg.shared.global [%0], [%1], 16;\n" ::"r"(s), "l"(gm));
}

// ---------------- weight quantization (ref-exact) ----------------
__global__ void reduce_abs_kernel(const float* __restrict__ W) {
    double s = 0.0;
    for (int i = blockIdx.x * blockDim.x + threadIdx.x; i < I_ * H_; i += gridDim.x * blockDim.x)
        s += (double)fabsf(W[i]);
    s = warp_sumd(s);
    __shared__ double sh[8];
    int lane = threadIdx.x & 31, wid = threadIdx.x >> 5;
    if (lane == 0) sh[wid] = s;
    __syncthreads();
    if (threadIdx.x == 0) {
        double t = 0.0;
        for (int i = 0; i < 8; i++) t += sh[i];
        g_partials[blockIdx.x] = t;
    }
}

__global__ void finalize_scale_kernel() {
    double s = g_partials[threadIdx.x];
    s = warp_sumd(s);
    __shared__ double sh[16];
    int lane = threadIdx.x & 31, wid = threadIdx.x >> 5;
    if (lane == 0) sh[wid] = s;
    __syncthreads();
    if (threadIdx.x == 0) {
        double t = 0.0;
        for (int i = 0; i < 16; i++) t += sh[i];
        // ref: mean in f32 = fl32(sum) / 2^21 (exact shift). CR sum via f64.
        float Sf = (float)t;
        float scale = Sf / 2097152.0f;           // exact
        g_sc[0] = scale;
        g_sc[1] = __fadd_rn(scale, 1e-5f);       // fl32(scale + EPS_Q)
    }
}

__global__ void quantize_kernel(const float* __restrict__ W) {
    int idx = blockIdx.x * 256 + threadIdx.x;    // W row-major [I][H]
    float d = g_sc[1];
    float t = rintf(W[idx] / d);                 // CR div + round-half-even (= jnp.round)
    t = fminf(1.f, fmaxf(-1.f, t));
    float wq = __fmul_rn(t, g_sc[0]);            // exact (t in {-1,0,1})
    int i = idx >> 11;                           // / H_
    int h = idx & (H_ - 1);
    g_WQ[(size_t)i * H_ + h] = wq;               // [i][h]
    g_W1T[(size_t)h * I_ + i] = wq;              // [h][i]
}

__global__ void init_kernel(const float* __restrict__ td, float* __restrict__ cur) {
    int idx = blockIdx.x * 256 + threadIdx.x;    // covers B_*H_
    cur[idx] = td[idx];
    g_inf_mem[idx] = 0.f;
    if (idx < B_ * I_) g_gen_mem[idx] = 0.f;
}

// ---------------- layer norm (eager-XLA-exact elementwise; CR stats) ----------------
// ref (eager, one primitive per op, all separately rounded):
//   mu = fl32(sum)/N; d = fl32(x-mu); var = fl32(sum(fl32(d*d)))/N;
//   rstd = fl32(1/fl32(sqrt(var+eps)));
//   y = fl32(fl32(fl32(x-mu)*rstd)*g) + b        <- NO fma anywhere
template <int N, int WHICH>
__global__ __launch_bounds__(256) void ln_kernel(const float* __restrict__ x,
                                                 const float* __restrict__ g,
                                                 const float* __restrict__ bb) {
    constexpr int PER = N / 256;
    const float* xr = x + (size_t)blockIdx.x * N;
    float* y = ((WHICH == 1) ? g_X1 : g_X2) + (size_t)blockIdx.x * N;
    float v[PER];
    double s = 0.0;
#pragma unroll
    for (int j = 0; j < PER; j++) {
        float t = xr[threadIdx.x + j * 256];
        v[j] = t;
        s += (double)t;
    }
    s = warp_sumd(s);
    __shared__ double sh[8];
    __shared__ float fmu, frstd;
    int lane = threadIdx.x & 31, wid = threadIdx.x >> 5;
    if (lane == 0) sh[wid] = s;
    __syncthreads();
    if (threadIdx.x == 0) {
        double a = 0.0;
        for (int i = 0; i < 8; i++) a += sh[i];
        float Sf = (float)a;                     // CR f32 sum
        fmu = Sf / (float)N;                     // exact (N power of 2)
    }
    __syncthreads();
    float mu = fmu;
    double s2 = 0.0;
#pragma unroll
    for (int j = 0; j < PER; j++) {
        float d = __fsub_rn(v[j], mu);
        float dd = __fmul_rn(d, d);
        s2 += (double)dd;
    }
    s2 = warp_sumd(s2);
    if (lane == 0) sh[wid] = s2;
    __syncthreads();
    if (threadIdx.x == 0) {
        double b2 = 0.0;
        for (int i = 0; i < 8; i++) b2 += sh[i];
        float S2f = (float)b2;                   // CR f32 sum of f32 dd's
        float var = S2f / (float)N;              // exact
        float vp = __fadd_rn(var, 1e-5f);
        frstd = __fdiv_rn(1.0f, __fsqrt_rn(vp)); // XLA rsqrt on CPU = 1/sqrt, both CR
    }
    __syncthreads();
    float rstd = frstd;
#pragma unroll
    for (int j = 0; j < PER; j++) {
        int c = threadIdx.x + j * 256;
        float t1 = __fsub_rn(v[j], mu);
        float t2 = __fmul_rn(t1, rstd);
        float t3 = __fmul_rn(t2, g[c]);          // separate mul (no fma!)
        y[c] = __fadd_rn(t3, bb[c]);             // separate add
    }
}

// ---------------- sequential-chain fp32 GEMM (Eigen-order) + fused LIF ----------------
// C[m,n] = fma-chain over k ascending of A[m,k]*W[k,n]  (A: [B_, KT], W: [KT, NT] k-major)
// Packed f32x2 lanes carry two adjacent n's; each lane is an independent IEEE chain.
// Epilogue: eager-XLA semantics — every mul/add separately rounded, NO contraction.
// EPI==1: LIF-gen + error(+pred/comb on last);  EPI==2: LIF-inf + current EMA(+comb)
template <int EPI, int KT, int NT>
__global__ __launch_bounds__(256) void gemm_seq_kernel(
    const float* __restrict__ bgen, const float* __restrict__ bu,
    const float* __restrict__ errscale, float* __restrict__ cur,
    float* __restrict__ err, float* __restrict__ comb, float* __restrict__ pred,
    int last) {
    const float* Ag = (EPI == 1) ? g_X1 : g_X2;
    const float* Wg = (EPI == 1) ? g_W1T : g_WQ;
    constexpr int BK = 16;
    __shared__ __align__(16) float sX[2][128][20];   // [m][k], row stride 20 (16B-aligned)
    __shared__ __align__(16) float sW[2][BK][132];   // [k][n]

    const int bm0 = blockIdx.y * 128, bn0 = blockIdx.x * 128;
    const int t = threadIdx.x;
    const int tx = t & 15, ty = t >> 4;
    const int m0 = ty * 8;        // local m base (8 rows)
    const int n0 = tx * 8;        // local n base (8 cols = 4 lane-pairs)

    unsigned long long acc[8][4];
#pragma unroll
    for (int j = 0; j < 8; j++)
#pragma unroll
        for (int p = 0; p < 4; p++) acc[j][p] = 0ull;

    auto load_stage = [&](int st, int kt) {
        int k0 = kt * BK;
        // X tile: 128 m x 16 k -> 512 cp16
#pragma unroll
        for (int rep = 0; rep < 2; rep++) {
            int q = t + rep * 256;
            int m = q >> 2, seg = (q & 3) << 2;
            cp16(&sX[st][m][seg], Ag + (size_t)(bm0 + m) * KT + k0 + seg);
        }
        // W tile: 16 k x 128 n -> 512 cp16
#pragma unroll
        for (int rep = 0; rep < 2; rep++) {
            int q = t + rep * 256;
            int kr = q >> 5, nseg = (q & 31) << 2;
            cp16(&sW[st][kr][nseg], Wg + (size_t)(k0 + kr) * NT + bn0 + nseg);
        }
        asm volatile("cp.async.commit_group;\n" ::);
    };

    constexpr int TILES = KT / BK;
    load_stage(0, 0);
#pragma unroll 1
    for (int kt = 0; kt < TILES; ++kt) {
        int buf = kt & 1;
        if (kt + 1 < TILES) {
            load_stage(buf ^ 1, kt + 1);
            asm volatile("cp.async.wait_group 1;\n" ::);
        } else {
            asm volatile("cp.async.wait_group 0;\n" ::);
        }
        __syncthreads();
#pragma unroll
        for (int kk = 0; kk < BK; ++kk) {
            unsigned long long wp[4];
            const float4* w4 = reinterpret_cast<const float4*>(&sW[buf][kk][n0]);
            float4 wa = w4[0], wb = w4[1];
            asm("mov.b64 %0, {%1, %2};" : "=l"(wp[0]) : "f"(wa.x), "f"(wa.y));
            asm("mov.b64 %0, {%1, %2};" : "=l"(wp[1]) : "f"(wa.z), "f"(wa.w));
            asm("mov.b64 %0, {%1, %2};" : "=l"(wp[2]) : "f"(wb.x), "f"(wb.y));
            asm("mov.b64 %0, {%1, %2};" : "=l"(wp[3]) : "f"(wb.z), "f"(wb.w));
#pragma unroll
            for (int j = 0; j < 8; j++) {
                unsigned long long xd = dup2(sX[buf][m0 + j][kk]);
#pragma unroll
                for (int p = 0; p < 4; p++) ffma2(acc[j][p], xd, wp[p]);
            }
        }
        __syncthreads();
    }

    // ---------------- epilogue (eager: separate rounding per op, NO fma) ----------------
#pragma unroll
    for (int j = 0; j < 8; j++) {
        int row = bm0 + m0 + j;
#pragma unroll
        for (int p = 0; p < 4; p++) {
            float c0, c1;
            asm("mov.b64 {%0, %1}, %2;" : "=f"(c0), "=f"(c1) : "l"(acc[j][p]));
            float cv[2] = {c0, c1};
#pragma unroll
            for (int q = 0; q < 2; q++) {
                int n = bn0 + n0 + p * 2 + q;
                size_t idx = (size_t)row * NT + n;
                if (EPI == 1) {
                    float es = *errscale;
                    float val = __fadd_rn(cv[q], bgen[n]);        // matmul + b_gen (add op)
                    float bm = __fmul_rn(BETA32, g_gen_mem[idx]); // mul op (rounds!)
                    float mem = __fadd_rn(bm, val);               // add op (rounds!)
                    bool sp = (mem >= 1.0f);
                    g_gen_mem[idx] = sp ? 0.f : mem;
                    float spk = sp ? 1.f : 0.f;
                    err[idx] = __fmul_rn(__fsub_rn(bu[idx], spk), es);
                    if (last) {
                        pred[idx] = spk;
                        comb[(size_t)row * (I_ + H_) + n] = mem;
                    }
                } else {
                    float bm = __fmul_rn(BETA32, g_inf_mem[idx]); // mul op (rounds!)
                    float mem = __fadd_rn(bm, cv[q]);             // add op (rounds!)
                    bool sp = (mem >= 1.0f);
                    g_inf_mem[idx] = sp ? 0.f : mem;
                    float spk = sp ? 1.f : 0.f;                   // kwta(spk)==spk
                    float c9 = __fmul_rn(cur[idx], 0.9f);         // mul op (rounds!)
                    float s1 = __fmul_rn(spk, 0.1f);              // mul op (exact here)
                    cur[idx] = __fadd_rn(c9, s1);                 // add op
                    if (last) comb[(size_t)row * (I_ + H_) + I_ + n] = mem;
                }
            }
        }
    }
}

// ---------------- launch ----------------
extern "C" void kernel_launch(void* const* d_in, const int* in_sizes, int n_in,
                              void* d_out, int out_size) {
    const float* bu   = (const float*)d_in[0];
    const float* td   = (const float*)d_in[1];
    const float* W    = (const float*)d_in[2];
    const float* bgen = (const float*)d_in[3];
    const float* gs   = (const float*)d_in[4];
    const float* bs   = (const float*)d_in[5];
    const float* ge   = (const float*)d_in[6];
    const float* be   = (const float*)d_in[7];
    const float* esc  = (const float*)d_in[8];
    float* out  = (float*)d_out;
    float* cur  = out;                                   // [B, H]
    float* err  = out + (size_t)B_ * H_;                 // [B, I]
    float* comb = err + (size_t)B_ * I_;                 // [B, I+H]
    float* pred = comb + (size_t)B_ * (I_ + H_);         // [B, I]

    reduce_abs_kernel<<<512, 256>>>(W);
    finalize_scale_kernel<<<1, 512>>>();
    quantize_kernel<<<(I_ * H_) / 256, 256>>>(W);
    init_kernel<<<(B_ * H_) / 256, 256>>>(td, cur);

    for (int s = 0; s < 5; ++s) {
        int last = (s == 4) ? 1 : 0;
        ln_kernel<H_, 1><<<B_, 256>>>(cur, gs, bs);
        gemm_seq_kernel<1, H_, I_><<<dim3(I_ / 128, B_ / 128), 256>>>(
            bgen, bu, esc, cur, err, comb, pred, last);
        ln_kernel<I_, 2><<<B_, 256>>>(err, ge, be);
        gemm_seq_kernel<2, I_, H_><<<dim3(H_ / 128, B_ / 128), 256>>>(
            bgen, bu, esc, cur, err, comb, pred, last);
    }
}